// round 1
// baseline (speedup 1.0000x reference)
#include <cuda_runtime.h>
#include <math.h>

#define NNODES 50000
#define NEDGES 800000
#define IN_DIM 256
#define OUT_DIM 64
#define HEADS 8
#define NH (HEADS*OUT_DIM)   // 512 fused output columns

// ---------------- scratch (device globals; no runtime allocation) ----------------
__device__ float    g_B[IN_DIM*NH];            // W transposed to [d][h*64+o]
__device__ float    g_u[16*IN_DIM];            // [j][d]; j 0-7: W_h a_src, 8-15: W_h a_dst
__device__ float    g_c[16];                   // bias dot terms
__device__ float    g_g[HEADS];                // softmax(gate)
__device__ float    g_Wh[(size_t)NNODES*NH];   // 102.4 MB
__device__ float    g_s[NNODES*16];            // per-node attention scalars
__device__ float    g_e[(size_t)NEDGES*HEADS]; // e values, then exp values in-place
__device__ unsigned g_mkey[HEADS];
__device__ float    g_Z[HEADS];
__device__ float    g_coef[HEADS];

// monotone float<->unsigned key for atomicMax on floats
__device__ __forceinline__ unsigned fkey(float f){
    unsigned b = __float_as_uint(f);
    return (b & 0x80000000u) ? ~b : (b | 0x80000000u);
}
__device__ __forceinline__ float fdec(unsigned k){
    return (k & 0x80000000u) ? __uint_as_float(k ^ 0x80000000u) : __uint_as_float(~k);
}

// packed f32x2 helpers
__device__ __forceinline__ unsigned long long dup2(float a){
    unsigned long long r;
    asm("mov.b64 %0, {%1, %1};" : "=l"(r) : "r"(__float_as_uint(a)));
    return r;
}
__device__ __forceinline__ void fma2(unsigned long long &acc, unsigned long long a, unsigned long long b){
    asm("fma.rn.f32x2 %0, %1, %2, %0;" : "+l"(acc) : "l"(a), "l"(b));
}
__device__ __forceinline__ void unpack2(unsigned long long v, float &lo, float &hi){
    unsigned l, h;
    asm("mov.b64 {%0, %1}, %2;" : "=r"(l), "=r"(h) : "l"(v));
    lo = __uint_as_float(l); hi = __uint_as_float(h);
}

// ---------------- kernels ----------------

__global__ void k_init(float* __restrict__ out){
    int i = blockIdx.x*blockDim.x + threadIdx.x;
    if (i < NNODES*OUT_DIM) out[i] = 0.f;
    if (blockIdx.x == 0 && threadIdx.x < HEADS){
        g_Z[threadIdx.x]    = 0.f;
        g_mkey[threadIdx.x] = 0u;
    }
}

__global__ void k_prep(const float* __restrict__ W, const float* __restrict__ b,
                       const float* __restrict__ a, const float* __restrict__ gate){
    int tid = blockIdx.x*blockDim.x + threadIdx.x;
    int stride = gridDim.x*blockDim.x;
    // transpose W: g_B[d][h*64+o]
    for (int idx = tid; idx < HEADS*IN_DIM*OUT_DIM; idx += stride){
        int h = idx / (IN_DIM*OUT_DIM);
        int r = idx - h*IN_DIM*OUT_DIM;
        int d = r / OUT_DIM;
        int o = r - d*OUT_DIM;
        g_B[d*NH + h*OUT_DIM + o] = W[idx];
    }
    // u[j][d] = sum_o W[h][d][o] * a[h][off+o]
    for (int idx = tid; idx < 16*IN_DIM; idx += stride){
        int j = idx / IN_DIM;
        int d = idx - j*IN_DIM;
        int h = j & 7;
        int off = (j < 8) ? 0 : OUT_DIM;
        const float* Wp = W + (size_t)h*IN_DIM*OUT_DIM + d*OUT_DIM;
        const float* ap = a + h*2*OUT_DIM + off;
        float acc = 0.f;
        #pragma unroll 8
        for (int o = 0; o < OUT_DIM; o++) acc += Wp[o]*ap[o];
        g_u[idx] = acc;
    }
    if (blockIdx.x == 0){
        if (threadIdx.x < 16){
            int j = threadIdx.x; int h = j & 7; int off = (j < 8) ? 0 : OUT_DIM;
            float acc = 0.f;
            for (int o = 0; o < OUT_DIM; o++) acc += b[h*OUT_DIM+o]*a[h*2*OUT_DIM+off+o];
            g_c[j] = acc;
        }
        if (threadIdx.x == 0){
            float m = -1e30f;
            for (int h = 0; h < HEADS; h++) m = fmaxf(m, gate[h]);
            float ex[HEADS]; float z = 0.f;
            for (int h = 0; h < HEADS; h++){ ex[h] = __expf(gate[h]-m); z += ex[h]; }
            for (int h = 0; h < HEADS; h++) g_g[h] = ex[h]/z;
        }
    }
}

// Wh[n][512] = x[n][256] @ g_B[256][512] + bias. 128x128 block tile, 8x8 thread
// microtile with packed fma.rn.f32x2 (2x FFMA throughput).
__global__ __launch_bounds__(256,2) void k_gemm(const float* __restrict__ x,
                                                const float* __restrict__ bias){
    __shared__ float As[16][128];   // transposed x tile
    __shared__ float Bs[16][128];
    int tid = threadIdx.x;
    int m0 = blockIdx.x*128;
    int n0 = blockIdx.y*128;
    int ty = tid >> 4, tx = tid & 15;

    unsigned long long acc[8][4];
    #pragma unroll
    for (int i = 0; i < 8; i++)
        #pragma unroll
        for (int j = 0; j < 4; j++) acc[i][j] = 0ull;

    for (int k0 = 0; k0 < IN_DIM; k0 += 16){
        // load A tile (128 rows x 16 k), store transposed
        #pragma unroll
        for (int i = 0; i < 2; i++){
            int idx = tid*2 + i;            // 0..511
            int r   = idx >> 2;             // 0..127
            int c4  = (idx & 3) * 4;        // 0,4,8,12
            int gm  = m0 + r;
            float4 v = make_float4(0.f,0.f,0.f,0.f);
            if (gm < NNODES)
                v = *reinterpret_cast<const float4*>(x + (size_t)gm*IN_DIM + k0 + c4);
            As[c4+0][r] = v.x; As[c4+1][r] = v.y; As[c4+2][r] = v.z; As[c4+3][r] = v.w;
        }
        // load B tile (16 k x 128 n)
        #pragma unroll
        for (int i = 0; i < 2; i++){
            int idx = tid*2 + i;
            int kk  = idx >> 5;             // 0..15
            int nn  = (idx & 31) * 4;
            *reinterpret_cast<float4*>(&Bs[kk][nn]) =
                *reinterpret_cast<const float4*>(g_B + (size_t)(k0+kk)*NH + n0 + nn);
        }
        __syncthreads();
        #pragma unroll
        for (int k = 0; k < 16; k++){
            float4 a0 = *reinterpret_cast<const float4*>(&As[k][ty*8]);
            float4 a1 = *reinterpret_cast<const float4*>(&As[k][ty*8+4]);
            unsigned long long a2[8];
            a2[0]=dup2(a0.x); a2[1]=dup2(a0.y); a2[2]=dup2(a0.z); a2[3]=dup2(a0.w);
            a2[4]=dup2(a1.x); a2[5]=dup2(a1.y); a2[6]=dup2(a1.z); a2[7]=dup2(a1.w);
            unsigned long long b2[4];
            #pragma unroll
            for (int j = 0; j < 4; j++)
                b2[j] = *reinterpret_cast<const unsigned long long*>(&Bs[k][tx*8 + j*2]);
            #pragma unroll
            for (int i = 0; i < 8; i++)
                #pragma unroll
                for (int j = 0; j < 4; j++)
                    fma2(acc[i][j], a2[i], b2[j]);
        }
        __syncthreads();
    }
    // epilogue: add bias, store
    #pragma unroll
    for (int i = 0; i < 8; i++){
        int gm = m0 + ty*8 + i;
        if (gm >= NNODES) break;
        float* dst = g_Wh + (size_t)gm*NH + n0 + tx*8;
        #pragma unroll
        for (int j = 0; j < 4; j++){
            float lo, hi; unpack2(acc[i][j], lo, hi);
            int gc = n0 + tx*8 + j*2;
            float2 r; r.x = lo + bias[gc]; r.y = hi + bias[gc+1];
            *reinterpret_cast<float2*>(dst + j*2) = r;
        }
    }
}

// per-node attention scalars: s[n][j] = x[n] . u[j] + c[j] ; warp per node
__global__ void k_s(const float* __restrict__ x){
    __shared__ float su[16*IN_DIM];
    int tid = threadIdx.x;
    for (int i = tid; i < 16*IN_DIM; i += blockDim.x) su[i] = g_u[i];
    __syncthreads();
    int warp = tid >> 5, lane = tid & 31;
    int n = blockIdx.x*8 + warp;
    if (n >= NNODES) return;
    const float* xp = x + (size_t)n*IN_DIM + lane*8;
    float4 v0 = *reinterpret_cast<const float4*>(xp);
    float4 v1 = *reinterpret_cast<const float4*>(xp+4);
    float xv[8] = {v0.x,v0.y,v0.z,v0.w,v1.x,v1.y,v1.z,v1.w};
    float p[16];
    #pragma unroll
    for (int j = 0; j < 16; j++){
        const float* up = su + j*IN_DIM + lane*8;
        float acc = 0.f;
        #pragma unroll
        for (int i = 0; i < 8; i++) acc += xv[i]*up[i];
        p[j] = acc;
    }
    #pragma unroll
    for (int j = 0; j < 16; j++)
        #pragma unroll
        for (int off = 16; off; off >>= 1)
            p[j] += __shfl_xor_sync(0xffffffffu, p[j], off);
    if (lane < 16) g_s[n*16 + lane] = p[lane] + g_c[lane];
}

// pass 1 over edges: e = leaky_relu(s_src[row]+s_dst[col]); track global max per head
__global__ void k_e_max(const int* __restrict__ ei){
    __shared__ unsigned skey[8];
    if (threadIdx.x < 8) skey[threadIdx.x] = 0u;
    __syncthreads();
    int e = blockIdx.x*blockDim.x + threadIdx.x;
    float ev[8];
    if (e < NEDGES){
        int row = ei[e], col = ei[NEDGES + e];
        float4 s0 = *reinterpret_cast<const float4*>(g_s + row*16);
        float4 s1 = *reinterpret_cast<const float4*>(g_s + row*16 + 4);
        float4 d0 = *reinterpret_cast<const float4*>(g_s + col*16 + 8);
        float4 d1 = *reinterpret_cast<const float4*>(g_s + col*16 + 12);
        float sv[8] = {s0.x,s0.y,s0.z,s0.w,s1.x,s1.y,s1.z,s1.w};
        float dv[8] = {d0.x,d0.y,d0.z,d0.w,d1.x,d1.y,d1.z,d1.w};
        #pragma unroll
        for (int h = 0; h < 8; h++){
            float t = sv[h] + dv[h];
            ev[h] = t > 0.f ? t : 0.01f*t;
        }
        *reinterpret_cast<float4*>(g_e + (size_t)e*8)     = make_float4(ev[0],ev[1],ev[2],ev[3]);
        *reinterpret_cast<float4*>(g_e + (size_t)e*8 + 4) = make_float4(ev[4],ev[5],ev[6],ev[7]);
    } else {
        #pragma unroll
        for (int h = 0; h < 8; h++) ev[h] = -1e30f;
    }
    #pragma unroll
    for (int h = 0; h < 8; h++)
        #pragma unroll
        for (int off = 16; off; off >>= 1)
            ev[h] = fmaxf(ev[h], __shfl_xor_sync(0xffffffffu, ev[h], off));
    if ((threadIdx.x & 31) == 0){
        #pragma unroll
        for (int h = 0; h < 8; h++) atomicMax(&skey[h], fkey(ev[h]));
    }
    __syncthreads();
    if (threadIdx.x < 8) atomicMax(&g_mkey[threadIdx.x], skey[threadIdx.x]);
}

// pass 2: exp(e - max) stored in place; accumulate per-head Z
__global__ void k_e_sum(){
    __shared__ float ssum[8];
    if (threadIdx.x < 8) ssum[threadIdx.x] = 0.f;
    __syncthreads();
    int e = blockIdx.x*blockDim.x + threadIdx.x;
    float m[8];
    #pragma unroll
    for (int h = 0; h < 8; h++) m[h] = fdec(g_mkey[h]);
    float ex[8];
    if (e < NEDGES){
        float4 v0 = *reinterpret_cast<const float4*>(g_e + (size_t)e*8);
        float4 v1 = *reinterpret_cast<const float4*>(g_e + (size_t)e*8 + 4);
        float v[8] = {v0.x,v0.y,v0.z,v0.w,v1.x,v1.y,v1.z,v1.w};
        #pragma unroll
        for (int h = 0; h < 8; h++) ex[h] = __expf(v[h] - m[h]);
        *reinterpret_cast<float4*>(g_e + (size_t)e*8)     = make_float4(ex[0],ex[1],ex[2],ex[3]);
        *reinterpret_cast<float4*>(g_e + (size_t)e*8 + 4) = make_float4(ex[4],ex[5],ex[6],ex[7]);
    } else {
        #pragma unroll
        for (int h = 0; h < 8; h++) ex[h] = 0.f;
    }
    #pragma unroll
    for (int h = 0; h < 8; h++)
        #pragma unroll
        for (int off = 16; off; off >>= 1)
            ex[h] += __shfl_xor_sync(0xffffffffu, ex[h], off);
    if ((threadIdx.x & 31) == 0){
        #pragma unroll
        for (int h = 0; h < 8; h++) atomicAdd(&ssum[h], ex[h]);
    }
    __syncthreads();
    if (threadIdx.x < 8) atomicAdd(&g_Z[threadIdx.x], ssum[threadIdx.x]);
}

__global__ void k_coef(){
    int t = threadIdx.x;
    if (t < HEADS) g_coef[t] = g_g[t] / g_Z[t];
}

// warp per edge: gather Wh[col] (2KB, mostly L2-resident), head-combine, RED into out[row]
__global__ __launch_bounds__(256) void k_scatter(const int* __restrict__ ei,
                                                 float* __restrict__ out){
    __shared__ float scoef[8];
    if (threadIdx.x < 8) scoef[threadIdx.x] = g_coef[threadIdx.x];
    __syncthreads();
    int warp = threadIdx.x >> 5, lane = threadIdx.x & 31;
    int e = blockIdx.x*8 + warp;
    if (e >= NEDGES) return;
    int row = ei[e], col = ei[NEDGES + e];
    float wv = 0.f;
    if (lane < 8) wv = scoef[lane] * g_e[(size_t)e*8 + lane];
    const float* whp = g_Wh + (size_t)col*NH;
    float acc0 = 0.f, acc1 = 0.f;
    #pragma unroll
    for (int h = 0; h < 8; h++){
        float w = __shfl_sync(0xffffffffu, wv, h);
        acc0 += w * whp[h*64 + lane];
        acc1 += w * whp[h*64 + 32 + lane];
    }
    atomicAdd(out + (size_t)row*64 + lane,      acc0);
    atomicAdd(out + (size_t)row*64 + 32 + lane, acc1);
}

// ---------------- launch ----------------
extern "C" void kernel_launch(void* const* d_in, const int* in_sizes, int n_in,
                              void* d_out, int out_size){
    const float* x    = (const float*)d_in[0];
    const int*   ei   = (const int*)  d_in[1];
    const float* W    = (const float*)d_in[2];
    const float* b    = (const float*)d_in[3];
    const float* a    = (const float*)d_in[4];
    const float* gate = (const float*)d_in[5];
    float* out = (float*)d_out;

    k_init<<<(NNODES*OUT_DIM + 255)/256, 256>>>(out);
    k_prep<<<64, 256>>>(W, b, a, gate);
    dim3 gg((NNODES + 127)/128, NH/128);
    k_gemm<<<gg, 256>>>(x, b);
    k_s<<<(NNODES + 7)/8, 256>>>(x);
    k_e_max<<<(NEDGES + 255)/256, 256>>>(ei);
    k_e_sum<<<(NEDGES + 255)/256, 256>>>();
    k_coef<<<1, 8>>>();
    k_scatter<<<(NEDGES + 7)/8, 256>>>(ei, out);
}

// round 3
// speedup vs baseline: 2.1287x; 2.1287x over previous
#include <cuda_runtime.h>
#include <cuda_bf16.h>
#include <stdint.h>

#define NNODES 50000
#define NPAD   50048            // 391 * 128
#define NEDGES 800000
#define IN_DIM 256
#define HEADS  8
#define NH     512

// ---------------- device scratch ----------------
__device__ __align__(128) __nv_bfloat16 g_Ah[(size_t)NPAD*IN_DIM];
__device__ __align__(128) __nv_bfloat16 g_Al[(size_t)NPAD*IN_DIM];
__device__ __align__(128) __nv_bfloat16 g_Bth[NH*IN_DIM];
__device__ __align__(128) __nv_bfloat16 g_Btl[NH*IN_DIM];
__device__ __align__(128) float g_Wh[(size_t)NNODES*NH];      // 102.4 MB
__device__ __align__(16)  float g_s[NNODES*16];
__device__ __align__(16)  float g_w[(size_t)NEDGES*HEADS];    // sorted exp weights
__device__ unsigned g_mkey[16];
__device__ float g_Z[HEADS];
__device__ float g_gate[HEADS];
__device__ float g_coef[HEADS];
__device__ int g_cnt[NNODES];
__device__ int g_colptr[NNODES+1];
__device__ int g_cur[NNODES];
__device__ int g_bsum[256];
__device__ int g_srow[NEDGES];
__device__ int g_scol[NEDGES];

// ---------------- helpers ----------------
__device__ __forceinline__ unsigned fkey(float f){
    unsigned b = __float_as_uint(f);
    return (b & 0x80000000u) ? ~b : (b | 0x80000000u);
}
__device__ __forceinline__ float fdec(unsigned k){
    return (k & 0x80000000u) ? __uint_as_float(k ^ 0x80000000u) : __uint_as_float(~k);
}
__device__ __forceinline__ uint32_t s2u(const void* p){
    return (uint32_t)__cvta_generic_to_shared(p);
}
__device__ __forceinline__ void cpa16(uint32_t dst, const void* src){
    asm volatile("cp.async.cg.shared.global [%0], [%1], 16;" :: "r"(dst), "l"(src));
}
__device__ __forceinline__ void ldsm4(uint32_t* r, uint32_t addr){
    asm volatile("ldmatrix.sync.aligned.m8n8.x4.shared.b16 {%0,%1,%2,%3}, [%4];"
        : "=r"(r[0]), "=r"(r[1]), "=r"(r[2]), "=r"(r[3]) : "r"(addr));
}
__device__ __forceinline__ void mma_bf16(float* d, const uint32_t* a, uint32_t b0, uint32_t b1){
    asm volatile("mma.sync.aligned.m16n8k16.row.col.f32.bf16.bf16.f32 "
        "{%0,%1,%2,%3},{%4,%5,%6,%7},{%8,%9},{%0,%1,%2,%3};"
        : "+f"(d[0]), "+f"(d[1]), "+f"(d[2]), "+f"(d[3])
        : "r"(a[0]), "r"(a[1]), "r"(a[2]), "r"(a[3]), "r"(b0), "r"(b1));
}

// ---------------- setup kernels ----------------

__global__ void k_init(float* __restrict__ out){
    int i = blockIdx.x*blockDim.x + threadIdx.x;
    if (i < NNODES*64) out[i] = 0.f;
    if (i < NNODES)    g_cnt[i] = 0;
    if (blockIdx.x == 0){
        if (threadIdx.x < HEADS) g_Z[threadIdx.x] = 0.f;
        if (threadIdx.x < 16)    g_mkey[threadIdx.x] = 0u;
    }
}

// fp32 -> bf16 hi/lo split of x, padded to NPAD rows
__global__ void k_convert(const float* __restrict__ x){
    int i = blockIdx.x*blockDim.x + threadIdx.x;       // index of float4
    if (i >= NPAD*IN_DIM/4) return;
    int base = i*4;
    int row = base / IN_DIM;
    float4 v = make_float4(0.f,0.f,0.f,0.f);
    if (row < NNODES) v = *reinterpret_cast<const float4*>(x + base);
    float vv[4] = {v.x, v.y, v.z, v.w};
    unsigned short hb[4], lb[4];
#pragma unroll
    for (int j = 0; j < 4; j++){
        __nv_bfloat16 h = __float2bfloat16(vv[j]);
        __nv_bfloat16 l = __float2bfloat16(vv[j] - __bfloat162float(h));
        hb[j] = __bfloat16_as_ushort(h);
        lb[j] = __bfloat16_as_ushort(l);
    }
    uint2 ph = make_uint2((unsigned)hb[0] | ((unsigned)hb[1]<<16),
                          (unsigned)hb[2] | ((unsigned)hb[3]<<16));
    uint2 pl = make_uint2((unsigned)lb[0] | ((unsigned)lb[1]<<16),
                          (unsigned)lb[2] | ((unsigned)lb[3]<<16));
    *reinterpret_cast<uint2*>(reinterpret_cast<char*>(g_Ah) + (size_t)base*2) = ph;
    *reinterpret_cast<uint2*>(reinterpret_cast<char*>(g_Al) + (size_t)base*2) = pl;
}

// transpose W to Bt[n=h*64+o][d] bf16 hi/lo; gate softmax
__global__ void k_prep(const float* __restrict__ W, const float* __restrict__ gate){
    int tid = blockIdx.x*blockDim.x + threadIdx.x;
    int stride = gridDim.x*blockDim.x;
    for (int idx = tid; idx < NH*IN_DIM; idx += stride){
        int n = idx >> 8, d = idx & 255;
        int h = n >> 6, o = n & 63;
        float v = W[(size_t)h*IN_DIM*64 + d*64 + o];
        __nv_bfloat16 hb = __float2bfloat16(v);
        __nv_bfloat16 lb = __float2bfloat16(v - __bfloat162float(hb));
        g_Bth[idx] = hb;
        g_Btl[idx] = lb;
    }
    if (blockIdx.x == 0 && threadIdx.x == 0){
        float m = -1e30f;
        for (int h = 0; h < HEADS; h++) m = fmaxf(m, gate[h]);
        float ex[HEADS]; float z = 0.f;
        for (int h = 0; h < HEADS; h++){ ex[h] = __expf(gate[h]-m); z += ex[h]; }
        for (int h = 0; h < HEADS; h++) g_gate[h] = ex[h]/z;
    }
}

// ---------------- CSC build ----------------
__global__ void k_cnt(const int* __restrict__ ei){
    int e = blockIdx.x*blockDim.x + threadIdx.x;
    if (e < NEDGES) atomicAdd(&g_cnt[ei[NEDGES + e]], 1);
}
__global__ void k_scan1(){
    __shared__ int sd[256];
    int tid = threadIdx.x;
    int i = blockIdx.x*256 + tid;
    int v = (i < NNODES) ? g_cnt[i] : 0;
    sd[tid] = v; __syncthreads();
    for (int off = 1; off < 256; off <<= 1){
        int t = (tid >= off) ? sd[tid - off] : 0;
        __syncthreads();
        sd[tid] += t;
        __syncthreads();
    }
    if (i < NNODES) g_colptr[i] = sd[tid] - v;
    if (tid == 255) g_bsum[blockIdx.x] = sd[255];
}
__global__ void k_scan2(){
    __shared__ int sd[256];
    int tid = threadIdx.x;
    const int nb = (NNODES + 255)/256;
    int v = (tid < nb) ? g_bsum[tid] : 0;
    sd[tid] = v; __syncthreads();
    for (int off = 1; off < 256; off <<= 1){
        int t = (tid >= off) ? sd[tid - off] : 0;
        __syncthreads();
        sd[tid] += t;
        __syncthreads();
    }
    if (tid < nb) g_bsum[tid] = sd[tid] - v;
}
__global__ void k_scan3(){
    int i = blockIdx.x*blockDim.x + threadIdx.x;
    if (i < NNODES){
        int p = g_colptr[i] + g_bsum[i >> 8];
        g_colptr[i] = p;
        g_cur[i]    = p;
    }
    if (i == 0) g_colptr[NNODES] = NEDGES;
}
__global__ void k_reorder(const int* __restrict__ ei){
    int e = blockIdx.x*blockDim.x + threadIdx.x;
    if (e >= NEDGES) return;
    int row = ei[e], col = ei[NEDGES + e];
    int pos = atomicAdd(&g_cur[col], 1);
    g_srow[pos] = row;
    g_scol[pos] = col;
}

// ---------------- HMMA GEMM: Wh = x @ Bt^T (3-pass bf16 split, fp32 acc) ----------------
// CTA 128x128, 8 warps (2x4), warp tile 64x32, K-chunk 32, double-buffered cp.async.
__device__ __forceinline__ void load_tile(uint32_t dstbase, const __nv_bfloat16* __restrict__ src,
                                          int tid){
#pragma unroll
    for (int i = 0; i < 2; i++){
        int idx = tid + i*256;
        int r = idx >> 2, q = idx & 3;
        uint32_t off = (uint32_t)(r*64 + ((q ^ ((r >> 1) & 3)) << 4));
        cpa16(dstbase + off, src + (size_t)r*IN_DIM + q*8);
    }
}

__global__ __launch_bounds__(256) void k_gemm(const float* __restrict__ bias,
                                              const float* __restrict__ a_vec){
    __shared__ __nv_bfloat16 sA[2][128*32];
    __shared__ __nv_bfloat16 sB[2][128*32];
    __shared__ float s_bias[512];
    __shared__ float s_a[1024];
    __shared__ float s_sm[128*16];
    __shared__ unsigned s_mk[16];

    int tid = threadIdx.x, wid = tid >> 5, lane = tid & 31;
    int wm = (wid >> 2)*64, wn = (wid & 3)*32;
    int m0 = blockIdx.x*128, n0 = blockIdx.y*128;

    for (int i = tid; i < 512;  i += 256) s_bias[i] = bias[i];
    for (int i = tid; i < 1024; i += 256) s_a[i]    = a_vec[i];
    for (int i = tid; i < 2048; i += 256) s_sm[i]   = 0.f;
    if (tid < 16) s_mk[tid] = 0u;

    float d[4][4][4];
#pragma unroll
    for (int mi = 0; mi < 4; mi++)
#pragma unroll
        for (int ni = 0; ni < 4; ni++)
#pragma unroll
            for (int k = 0; k < 4; k++) d[mi][ni][k] = 0.f;

    // chunk c (0..23): pass p=c>>3 (0:Ah*Bh 1:Al*Bh 2:Ah*Bl), k-eighth q=c&7
    const __nv_bfloat16* Abase = g_Ah  + (size_t)m0*IN_DIM;
    const __nv_bfloat16* Albase= g_Al  + (size_t)m0*IN_DIM;
    const __nv_bfloat16* Bbase = g_Bth + (size_t)n0*IN_DIM;
    const __nv_bfloat16* Blbase= g_Btl + (size_t)n0*IN_DIM;

    load_tile(s2u(sA[0]), Abase, tid);
    load_tile(s2u(sB[0]), Bbase, tid);
    asm volatile("cp.async.commit_group;" ::: "memory");

    for (int c = 0; c < 24; c++){
        if (c < 23){
            int cn = c + 1;
            int p = cn >> 3, q = cn & 7;
            const __nv_bfloat16* As = ((p == 1) ? Albase : Abase) + q*32;
            const __nv_bfloat16* Bs = ((p == 2) ? Blbase : Bbase) + q*32;
            int st = cn & 1;
            load_tile(s2u(sA[st]), As, tid);
            load_tile(s2u(sB[st]), Bs, tid);
            asm volatile("cp.async.commit_group;" ::: "memory");
            asm volatile("cp.async.wait_group 1;" ::: "memory");
        } else {
            asm volatile("cp.async.wait_group 0;" ::: "memory");
        }
        __syncthreads();
        int st = c & 1;
        uint32_t sAb = s2u(sA[st]), sBb = s2u(sB[st]);
#pragma unroll
        for (int ks = 0; ks < 2; ks++){
            uint32_t af[4][4], bf[2][4];
            int q = ks*2 + (lane >> 4);
#pragma unroll
            for (int mi = 0; mi < 4; mi++){
                int row = wm + mi*16 + (lane & 15);
                ldsm4(af[mi], sAb + row*64 + ((q ^ ((row >> 1) & 3)) << 4));
            }
#pragma unroll
            for (int bi = 0; bi < 2; bi++){
                int row = wn + bi*16 + (lane & 15);
                ldsm4(bf[bi], sBb + row*64 + ((q ^ ((row >> 1) & 3)) << 4));
            }
#pragma unroll
            for (int mi = 0; mi < 4; mi++)
#pragma unroll
                for (int ni = 0; ni < 4; ni++){
                    int bi = ni >> 1, sub = ni & 1;
                    mma_bf16(d[mi][ni], af[mi], bf[bi][sub], bf[bi][sub + 2]);
                }
        }
        __syncthreads();
    }

    // -------- epilogue: bias, Wh store, fused s-dots + node max --------
    int h = (n0 + wn) >> 6;                 // single head per warp (wn multiple of 32)
    const float* aS = s_a + h*128;
    const float* aD = s_a + h*128 + 64;
    float accS[4][2], accD[4][2];
#pragma unroll
    for (int mi = 0; mi < 4; mi++){ accS[mi][0]=accS[mi][1]=accD[mi][0]=accD[mi][1]=0.f; }

#pragma unroll
    for (int mi = 0; mi < 4; mi++){
#pragma unroll
        for (int ni = 0; ni < 4; ni++){
            int C = wn + ni*8 + (lane & 3)*2;
            int o = C & 63;
            float b0 = s_bias[n0 + C], b1 = s_bias[n0 + C + 1];
#pragma unroll
            for (int rr = 0; rr < 2; rr++){
                float v0 = d[mi][ni][rr*2 + 0] + b0;
                float v1 = d[mi][ni][rr*2 + 1] + b1;
                int R = wm + mi*16 + (lane >> 2) + rr*8;
                int gm = m0 + R;
                if (gm < NNODES){
                    float2 st2; st2.x = v0; st2.y = v1;
                    *reinterpret_cast<float2*>(g_Wh + (size_t)gm*NH + n0 + C) = st2;
                }
                accS[mi][rr] += v0*aS[o] + v1*aS[o+1];
                accD[mi][rr] += v0*aD[o] + v1*aD[o+1];
            }
        }
    }
    // reduce across the 4 lanes sharing each row, accumulate into s_sm
#pragma unroll
    for (int mi = 0; mi < 4; mi++)
#pragma unroll
        for (int rr = 0; rr < 2; rr++){
            float vs = accS[mi][rr], vd = accD[mi][rr];
            vs += __shfl_xor_sync(0xffffffffu, vs, 1);
            vs += __shfl_xor_sync(0xffffffffu, vs, 2);
            vd += __shfl_xor_sync(0xffffffffu, vd, 1);
            vd += __shfl_xor_sync(0xffffffffu, vd, 2);
            if ((lane & 3) == 0){
                int R = wm + mi*16 + (lane >> 2) + rr*8;
                atomicAdd(&s_sm[R*16 + h],     vs);
                atomicAdd(&s_sm[R*16 + 8 + h], vd);
            }
        }
    __syncthreads();
    // write s (only this CTA's 2 heads: h0, h0+1) + per-head node max
    int h0 = n0 >> 6;
    for (int i = tid; i < 512; i += 256){
        int r = i >> 2, jj = i & 3;
        int j = h0 + (jj & 1) + (jj >> 1)*8;
        int gm = m0 + r;
        if (gm < NNODES){
            float v = s_sm[r*16 + j];
            g_s[gm*16 + j] = v;
            atomicMax(&s_mk[j], fkey(v));
        }
    }
    __syncthreads();
    if (tid < 4){
        int j = h0 + (tid & 1) + (tid >> 1)*8;
        unsigned k = s_mk[j];
        if (k) atomicMax(&g_mkey[j], k);
    }
}

// ---------------- single edge pass (sorted order): exp weights + Z ----------------
__global__ void k_e(){
    __shared__ float sM[8];
    __shared__ float ssum[8];
    if (threadIdx.x < 8){
        float m = fdec(g_mkey[threadIdx.x]) + fdec(g_mkey[8 + threadIdx.x]);
        sM[threadIdx.x] = (m > 0.f) ? m : 0.01f*m;   // leaky(bound) >= leaky(e)
        ssum[threadIdx.x] = 0.f;
    }
    __syncthreads();
    int p = blockIdx.x*blockDim.x + threadIdx.x;
    int row = g_srow[p], col = g_scol[p];
    float4 s0 = *reinterpret_cast<const float4*>(g_s + row*16);
    float4 s1 = *reinterpret_cast<const float4*>(g_s + row*16 + 4);
    float4 d0 = *reinterpret_cast<const float4*>(g_s + col*16 + 8);
    float4 d1 = *reinterpret_cast<const float4*>(g_s + col*16 + 12);
    float sv[8] = {s0.x,s0.y,s0.z,s0.w,s1.x,s1.y,s1.z,s1.w};
    float dv[8] = {d0.x,d0.y,d0.z,d0.w,d1.x,d1.y,d1.z,d1.w};
    float ex[8];
#pragma unroll
    for (int h = 0; h < 8; h++){
        float t = sv[h] + dv[h];
        t = (t > 0.f) ? t : 0.01f*t;
        ex[h] = __expf(t - sM[h]);
    }
    *reinterpret_cast<float4*>(g_w + (size_t)p*8)     = make_float4(ex[0],ex[1],ex[2],ex[3]);
    *reinterpret_cast<float4*>(g_w + (size_t)p*8 + 4) = make_float4(ex[4],ex[5],ex[6],ex[7]);
#pragma unroll
    for (int h = 0; h < 8; h++)
#pragma unroll
        for (int off = 16; off; off >>= 1)
            ex[h] += __shfl_xor_sync(0xffffffffu, ex[h], off);
    if ((threadIdx.x & 31) == 0){
#pragma unroll
        for (int h = 0; h < 8; h++) atomicAdd(&ssum[h], ex[h]);
    }
    __syncthreads();
    if (threadIdx.x < 8) atomicAdd(&g_Z[threadIdx.x], ssum[threadIdx.x]);
}

__global__ void k_coef(){
    if (threadIdx.x < HEADS) g_coef[threadIdx.x] = g_gate[threadIdx.x] / g_Z[threadIdx.x];
}

// ---------------- CSC scatter: warp per col, Wh row loaded once, coalesced RED ----------------
__global__ __launch_bounds__(256) void k_scatter(float* __restrict__ out){
    __shared__ float sc[8];
    if (threadIdx.x < 8) sc[threadIdx.x] = g_coef[threadIdx.x];
    __syncthreads();
    int warp = threadIdx.x >> 5, lane = threadIdx.x & 31;
    int c = blockIdx.x*8 + warp;
    if (c >= NNODES) return;
    int p0 = g_colptr[c], p1 = g_colptr[c+1];
    if (p0 == p1) return;
    const float* wp = g_Wh + (size_t)c*NH;
    float whv[16];
#pragma unroll
    for (int h = 0; h < 8; h++){
        whv[h]     = wp[h*64 + lane];
        whv[8 + h] = wp[h*64 + 32 + lane];
    }
    for (int p = p0; p < p1; p++){
        float wv = 0.f;
        if (lane < 8) wv = sc[lane] * g_w[(size_t)p*8 + lane];
        float acc0 = 0.f, acc1 = 0.f;
#pragma unroll
        for (int h = 0; h < 8; h++){
            float w = __shfl_sync(0xffffffffu, wv, h);
            acc0 += w * whv[h];
            acc1 += w * whv[8 + h];
        }
        int row = g_srow[p];
        atomicAdd(out + (size_t)row*64 + lane,      acc0);
        atomicAdd(out + (size_t)row*64 + 32 + lane, acc1);
    }
}

// ---------------- launch ----------------
extern "C" void kernel_launch(void* const* d_in, const int* in_sizes, int n_in,
                              void* d_out, int out_size){
    const float* x    = (const float*)d_in[0];
    const int*   ei   = (const int*)  d_in[1];
    const float* W    = (const float*)d_in[2];
    const float* b    = (const float*)d_in[3];
    const float* a    = (const float*)d_in[4];
    const float* gate = (const float*)d_in[5];
    float* out = (float*)d_out;

    k_init<<<(NNODES*64 + 255)/256, 256>>>(out);
    k_convert<<<(NPAD*IN_DIM/4 + 255)/256, 256>>>(x);
    k_prep<<<128, 256>>>(W, gate);
    k_cnt<<<NEDGES/256, 256>>>(ei);
    k_scan1<<<(NNODES + 255)/256, 256>>>();
    k_scan2<<<1, 256>>>();
    k_scan3<<<(NNODES + 255)/256, 256>>>();
    k_reorder<<<NEDGES/256, 256>>>(ei);
    dim3 gg(NPAD/128, 4);
    k_gemm<<<gg, 256>>>(b, a);
    k_e<<<NEDGES/256, 256>>>();
    k_coef<<<1, 8>>>();
    k_scatter<<<(NNODES + 7)/8, 256>>>(out);
}

// round 4
// speedup vs baseline: 2.4399x; 1.1462x over previous
#include <cuda_runtime.h>
#include <cuda_bf16.h>
#include <stdint.h>

#define NNODES 50000
#define NPAD   50048            // 391 * 128
#define NEDGES 800000
#define IN_DIM 256
#define HEADS  8
#define NH     512

// ---------------- device scratch ----------------
__device__ __align__(128) __nv_bfloat16 g_Ah[(size_t)NPAD*IN_DIM];
__device__ __align__(128) __nv_bfloat16 g_Al[(size_t)NPAD*IN_DIM];
__device__ __align__(128) __nv_bfloat16 g_Bth[NH*IN_DIM];
__device__ __align__(128) __nv_bfloat16 g_Btl[NH*IN_DIM];
__device__ __align__(128) float g_Wh[(size_t)NNODES*NH];      // 102.4 MB
__device__ __align__(16)  float g_s[NNODES*16];
__device__ __align__(16)  float g_w[(size_t)NEDGES*HEADS];    // sorted exp weights
__device__ unsigned g_mkey[16];
__device__ float g_Z[HEADS];
__device__ float g_gate[HEADS];
__device__ int g_cnt[NNODES];          // zeroed by scan1 of previous run / module load
__device__ int g_colptr[NNODES+1];
__device__ int g_cur[NNODES];
__device__ int g_bsum[256];
__device__ int g_srow[NEDGES];
__device__ int g_scol[NEDGES];

// ---------------- helpers ----------------
__device__ __forceinline__ unsigned fkey(float f){
    unsigned b = __float_as_uint(f);
    return (b & 0x80000000u) ? ~b : (b | 0x80000000u);
}
__device__ __forceinline__ float fdec(unsigned k){
    return (k & 0x80000000u) ? __uint_as_float(k ^ 0x80000000u) : __uint_as_float(~k);
}
__device__ __forceinline__ uint32_t s2u(const void* p){
    return (uint32_t)__cvta_generic_to_shared(p);
}
__device__ __forceinline__ void cpa16(uint32_t dst, const void* src){
    asm volatile("cp.async.cg.shared.global [%0], [%1], 16;" :: "r"(dst), "l"(src));
}
__device__ __forceinline__ void ldsm4(uint32_t* r, uint32_t addr){
    asm volatile("ldmatrix.sync.aligned.m8n8.x4.shared.b16 {%0,%1,%2,%3}, [%4];"
        : "=r"(r[0]), "=r"(r[1]), "=r"(r[2]), "=r"(r[3]) : "r"(addr));
}
__device__ __forceinline__ void mma_bf16(float* d, const uint32_t* a, uint32_t b0, uint32_t b1){
    asm volatile("mma.sync.aligned.m16n8k16.row.col.f32.bf16.bf16.f32 "
        "{%0,%1,%2,%3},{%4,%5,%6,%7},{%8,%9},{%0,%1,%2,%3};"
        : "+f"(d[0]), "+f"(d[1]), "+f"(d[2]), "+f"(d[3])
        : "r"(a[0]), "r"(a[1]), "r"(a[2]), "r"(a[3]), "r"(b0), "r"(b1));
}

// ---------------- fused setup: out-zero, misc-zero, convert, prep, edge-count ----------------
__global__ void k_setup(const float* __restrict__ x, const int* __restrict__ ei,
                        const float* __restrict__ W, const float* __restrict__ gate,
                        float* __restrict__ out){
    int tid = blockIdx.x*blockDim.x + threadIdx.x;
    if (tid < 8)  g_Z[tid] = 0.f;
    if (tid < 16) g_mkey[tid] = 0u;
    if (tid == 0){
        float m = -1e30f;
        for (int h = 0; h < HEADS; h++) m = fmaxf(m, gate[h]);
        float ex[HEADS]; float z = 0.f;
        for (int h = 0; h < HEADS; h++){ ex[h] = __expf(gate[h]-m); z += ex[h]; }
        for (int h = 0; h < HEADS; h++) g_gate[h] = ex[h]/z;
    }
    // zero output (50000*64 floats = 800000 float4)
    if (tid < NNODES*16)
        reinterpret_cast<float4*>(out)[tid] = make_float4(0.f,0.f,0.f,0.f);
    // edge count for CSC
    if (tid < NEDGES) atomicAdd(&g_cnt[ei[NEDGES + tid]], 1);
    // W transpose to Bt[n][d] bf16 hi/lo
    if (tid < NH*IN_DIM){
        int n = tid >> 8, d = tid & 255;
        int h = n >> 6, o = n & 63;
        float v = W[(size_t)h*IN_DIM*64 + d*64 + o];
        __nv_bfloat16 hb = __float2bfloat16(v);
        __nv_bfloat16 lb = __float2bfloat16(v - __bfloat162float(hb));
        g_Bth[tid] = hb;
        g_Btl[tid] = lb;
    }
    // x -> bf16 hi/lo, padded
    if (tid < NPAD*IN_DIM/4){
        int base = tid*4;
        int row = base / IN_DIM;
        float4 v = make_float4(0.f,0.f,0.f,0.f);
        if (row < NNODES) v = *reinterpret_cast<const float4*>(x + base);
        float vv[4] = {v.x, v.y, v.z, v.w};
        unsigned short hb[4], lb[4];
#pragma unroll
        for (int j = 0; j < 4; j++){
            __nv_bfloat16 h = __float2bfloat16(vv[j]);
            __nv_bfloat16 l = __float2bfloat16(vv[j] - __bfloat162float(h));
            hb[j] = __bfloat16_as_ushort(h);
            lb[j] = __bfloat16_as_ushort(l);
        }
        uint2 ph = make_uint2((unsigned)hb[0] | ((unsigned)hb[1]<<16),
                              (unsigned)hb[2] | ((unsigned)hb[3]<<16));
        uint2 pl = make_uint2((unsigned)lb[0] | ((unsigned)lb[1]<<16),
                              (unsigned)lb[2] | ((unsigned)lb[3]<<16));
        *reinterpret_cast<uint2*>(reinterpret_cast<char*>(g_Ah) + (size_t)base*2) = ph;
        *reinterpret_cast<uint2*>(reinterpret_cast<char*>(g_Al) + (size_t)base*2) = pl;
    }
}

// ---------------- CSC scans ----------------
__global__ void k_scan1(){
    __shared__ int sd[256];
    int tid = threadIdx.x;
    int i = blockIdx.x*256 + tid;
    int v = (i < NNODES) ? g_cnt[i] : 0;
    if (i < NNODES) g_cnt[i] = 0;          // re-zero for next run
    sd[tid] = v; __syncthreads();
    for (int off = 1; off < 256; off <<= 1){
        int t = (tid >= off) ? sd[tid - off] : 0;
        __syncthreads();
        sd[tid] += t;
        __syncthreads();
    }
    if (i < NNODES) g_colptr[i] = sd[tid] - v;
    if (tid == 255) g_bsum[blockIdx.x] = sd[255];
}
__global__ void k_scan2(){
    __shared__ int sd[256];
    int tid = threadIdx.x;
    const int nb = (NNODES + 255)/256;
    int v = (tid < nb) ? g_bsum[tid] : 0;
    sd[tid] = v; __syncthreads();
    for (int off = 1; off < 256; off <<= 1){
        int t = (tid >= off) ? sd[tid - off] : 0;
        __syncthreads();
        sd[tid] += t;
        __syncthreads();
    }
    if (tid < nb) g_bsum[tid] = sd[tid] - v;
}
__global__ void k_scan3(){
    int i = blockIdx.x*blockDim.x + threadIdx.x;
    if (i < NNODES){
        int p = g_colptr[i] + g_bsum[i >> 8];
        g_colptr[i] = p;
        g_cur[i]    = p;
    }
    if (i == 0) g_colptr[NNODES] = NEDGES;
}

// ---------------- big kernel: HMMA GEMM (4-stage pipe) + reorder in prologue ----------------
// dynamic smem layout (bytes)
#define OFF_A    0                      // 4 stages x 8192
#define OFF_B    32768                  // 4 stages x 8192
#define OFF_BIAS 65536                  // 512 f
#define OFF_SA   67584                  // 1024 f
#define OFF_SSM  71680                  // 128*16 f
#define OFF_SMK  79872                  // 16 u32
#define SMEM_BIG 79936

__device__ __forceinline__ void load_tile(uint32_t dstbase, const __nv_bfloat16* __restrict__ src,
                                          int tid){
#pragma unroll
    for (int i = 0; i < 2; i++){
        int idx = tid + i*256;
        int r = idx >> 2, q = idx & 3;
        uint32_t off = (uint32_t)(r*64 + ((q ^ ((r >> 1) & 3)) << 4));
        cpa16(dstbase + off, src + (size_t)r*IN_DIM + q*8);
    }
}

__device__ __forceinline__ void gemm_compute(uint32_t sAb, uint32_t sBb,
                                             int wm, int wn, int lane, float d[4][4][4]){
#pragma unroll
    for (int ks = 0; ks < 2; ks++){
        uint32_t af[4][4], bf[2][4];
        int q = ks*2 + (lane >> 4);
#pragma unroll
        for (int mi = 0; mi < 4; mi++){
            int row = wm + mi*16 + (lane & 15);
            ldsm4(af[mi], sAb + row*64 + ((q ^ ((row >> 1) & 3)) << 4));
        }
#pragma unroll
        for (int bi = 0; bi < 2; bi++){
            int row = wn + bi*16 + (lane & 15);
            ldsm4(bf[bi], sBb + row*64 + ((q ^ ((row >> 1) & 3)) << 4));
        }
#pragma unroll
        for (int mi = 0; mi < 4; mi++)
#pragma unroll
            for (int ni = 0; ni < 4; ni++){
                int bi = ni >> 1, sub = ni & 1;
                mma_bf16(d[mi][ni], af[mi], bf[bi][sub], bf[bi][sub + 2]);
            }
    }
}

__global__ __launch_bounds__(256,2) void k_big(const float* __restrict__ bias,
                                               const float* __restrict__ a_vec,
                                               const int* __restrict__ ei){
    extern __shared__ char smem[];
    uint32_t sb = s2u(smem);
    float*    s_bias = (float*)(smem + OFF_BIAS);
    float*    s_a    = (float*)(smem + OFF_SA);
    float*    s_sm   = (float*)(smem + OFF_SSM);
    unsigned* s_mk   = (unsigned*)(smem + OFF_SMK);

    int tid = threadIdx.x, wid = tid >> 5, lane = tid & 31;
    int wm = (wid >> 2)*64, wn = (wid & 3)*32;
    int m0 = blockIdx.x*128, n0 = blockIdx.y*128;

    for (int i = tid; i < 512;  i += 256) s_bias[i] = bias[i];
    for (int i = tid; i < 1024; i += 256) s_a[i]    = a_vec[i];
    for (int i = tid; i < 2048; i += 256) s_sm[i]   = 0.f;
    if (tid < 16) s_mk[tid] = 0u;

    float d[4][4][4];
#pragma unroll
    for (int mi = 0; mi < 4; mi++)
#pragma unroll
        for (int ni = 0; ni < 4; ni++)
#pragma unroll
            for (int k = 0; k < 4; k++) d[mi][ni][k] = 0.f;

    const __nv_bfloat16* Abase  = g_Ah  + (size_t)m0*IN_DIM;
    const __nv_bfloat16* Albase = g_Al  + (size_t)m0*IN_DIM;
    const __nv_bfloat16* Bbase  = g_Bth + (size_t)n0*IN_DIM;
    const __nv_bfloat16* Blbase = g_Btl + (size_t)n0*IN_DIM;

    // chunk c (0..23): pass p=c>>3 (0:Ah*Bh 1:Al*Bh 2:Ah*Bl), k-eighth q=c&7
    // prologue: stages 0..2
#pragma unroll
    for (int c = 0; c < 3; c++){
        const __nv_bfloat16* As = Abase + (c)*32;     // all prologue chunks are pass 0
        const __nv_bfloat16* Bs = Bbase + (c)*32;
        load_tile(sb + OFF_A + c*8192, As, tid);
        load_tile(sb + OFF_B + c*8192, Bs, tid);
        asm volatile("cp.async.commit_group;" ::: "memory");
    }

    // CSC reorder: 512 edges per CTA, hidden behind the first chunk loads
    {
        int cta = blockIdx.y*391 + blockIdx.x;
#pragma unroll
        for (int r = 0; r < 2; r++){
            int e = cta*512 + r*256 + tid;
            if (e < NEDGES){
                int row = ei[e], col = ei[NEDGES + e];
                int pos = atomicAdd(&g_cur[col], 1);
                g_srow[pos] = row;
                g_scol[pos] = col;
            }
        }
    }

    for (int c = 0; c < 24; c++){
        asm volatile("cp.async.wait_group 2;" ::: "memory");
        __syncthreads();
        int cn = c + 3;
        if (cn < 24){
            int p = cn >> 3, q = cn & 7;
            const __nv_bfloat16* As = ((p == 1) ? Albase : Abase) + q*32;
            const __nv_bfloat16* Bs = ((p == 2) ? Blbase : Bbase) + q*32;
            int st = cn & 3;
            load_tile(sb + OFF_A + st*8192, As, tid);
            load_tile(sb + OFF_B + st*8192, Bs, tid);
        }
        asm volatile("cp.async.commit_group;" ::: "memory");   // possibly empty group
        int st = c & 3;
        gemm_compute(sb + OFF_A + st*8192, sb + OFF_B + st*8192, wm, wn, lane, d);
    }

    // -------- epilogue: bias, Wh store, fused s-dots + node max --------
    int h = (n0 + wn) >> 6;                 // head handled by this warp
    const float* aS = s_a + h*128;
    const float* aD = s_a + h*128 + 64;
    float accS[4][2], accD[4][2];
#pragma unroll
    for (int mi = 0; mi < 4; mi++){ accS[mi][0]=accS[mi][1]=accD[mi][0]=accD[mi][1]=0.f; }

#pragma unroll
    for (int mi = 0; mi < 4; mi++){
#pragma unroll
        for (int ni = 0; ni < 4; ni++){
            int C = wn + ni*8 + (lane & 3)*2;
            int o = C & 63;
            float b0 = s_bias[n0 + C], b1 = s_bias[n0 + C + 1];
#pragma unroll
            for (int rr = 0; rr < 2; rr++){
                float v0 = d[mi][ni][rr*2 + 0] + b0;
                float v1 = d[mi][ni][rr*2 + 1] + b1;
                int R = wm + mi*16 + (lane >> 2) + rr*8;
                int gm = m0 + R;
                if (gm < NNODES){
                    float2 st2; st2.x = v0; st2.y = v1;
                    *reinterpret_cast<float2*>(g_Wh + (size_t)gm*NH + n0 + C) = st2;
                }
                accS[mi][rr] += v0*aS[o] + v1*aS[o+1];
                accD[mi][rr] += v0*aD[o] + v1*aD[o+1];
            }
        }
    }
#pragma unroll
    for (int mi = 0; mi < 4; mi++)
#pragma unroll
        for (int rr = 0; rr < 2; rr++){
            float vs = accS[mi][rr], vd = accD[mi][rr];
            vs += __shfl_xor_sync(0xffffffffu, vs, 1);
            vs += __shfl_xor_sync(0xffffffffu, vs, 2);
            vd += __shfl_xor_sync(0xffffffffu, vd, 1);
            vd += __shfl_xor_sync(0xffffffffu, vd, 2);
            if ((lane & 3) == 0){
                int R = wm + mi*16 + (lane >> 2) + rr*8;
                atomicAdd(&s_sm[R*16 + h],     vs);
                atomicAdd(&s_sm[R*16 + 8 + h], vd);
            }
        }
    __syncthreads();
    int h0 = n0 >> 6;
    for (int i = tid; i < 512; i += 256){
        int r = i >> 2, jj = i & 3;
        int j = h0 + (jj & 1) + (jj >> 1)*8;
        int gm = m0 + r;
        if (gm < NNODES){
            float v = s_sm[r*16 + j];
            g_s[gm*16 + j] = v;
            atomicMax(&s_mk[j], fkey(v));
        }
    }
    __syncthreads();
    if (tid < 4){
        int j = h0 + (tid & 1) + (tid >> 1)*8;
        unsigned k = s_mk[j];
        if (k) atomicMax(&g_mkey[j], k);
    }
}

// ---------------- single edge pass (sorted order): exp weights + Z ----------------
__global__ void k_e(){
    __shared__ float sM[8];
    __shared__ float ssum[8];
    if (threadIdx.x < 8){
        float m = fdec(g_mkey[threadIdx.x]) + fdec(g_mkey[8 + threadIdx.x]);
        sM[threadIdx.x] = (m > 0.f) ? m : 0.01f*m;   // leaky(bound) >= leaky(e)
        ssum[threadIdx.x] = 0.f;
    }
    __syncthreads();
    int p = blockIdx.x*blockDim.x + threadIdx.x;
    int row = g_srow[p], col = g_scol[p];
    float4 s0 = *reinterpret_cast<const float4*>(g_s + row*16);
    float4 s1 = *reinterpret_cast<const float4*>(g_s + row*16 + 4);
    float4 d0 = *reinterpret_cast<const float4*>(g_s + col*16 + 8);
    float4 d1 = *reinterpret_cast<const float4*>(g_s + col*16 + 12);
    float sv[8] = {s0.x,s0.y,s0.z,s0.w,s1.x,s1.y,s1.z,s1.w};
    float dv[8] = {d0.x,d0.y,d0.z,d0.w,d1.x,d1.y,d1.z,d1.w};
    float ex[8];
#pragma unroll
    for (int h = 0; h < 8; h++){
        float t = sv[h] + dv[h];
        t = (t > 0.f) ? t : 0.01f*t;
        ex[h] = __expf(t - sM[h]);
    }
    *reinterpret_cast<float4*>(g_w + (size_t)p*8)     = make_float4(ex[0],ex[1],ex[2],ex[3]);
    *reinterpret_cast<float4*>(g_w + (size_t)p*8 + 4) = make_float4(ex[4],ex[5],ex[6],ex[7]);
#pragma unroll
    for (int h = 0; h < 8; h++)
#pragma unroll
        for (int off = 16; off; off >>= 1)
            ex[h] += __shfl_xor_sync(0xffffffffu, ex[h], off);
    if ((threadIdx.x & 31) == 0){
#pragma unroll
        for (int h = 0; h < 8; h++) atomicAdd(&ssum[h], ex[h]);
    }
    __syncthreads();
    if (threadIdx.x < 8) atomicAdd(&g_Z[threadIdx.x], ssum[threadIdx.x]);
}

// ---------------- CSC scatter: warp per col, 2-edge unroll, coalesced RED ----------------
__global__ __launch_bounds__(256) void k_scatter(float* __restrict__ out){
    __shared__ float sc[8];
    if (threadIdx.x < 8) sc[threadIdx.x] = g_gate[threadIdx.x] / g_Z[threadIdx.x];
    __syncthreads();
    int warp = threadIdx.x >> 5, lane = threadIdx.x & 31;
    int c = blockIdx.x*8 + warp;
    if (c >= NNODES) return;
    int p0 = g_colptr[c], p1 = g_colptr[c+1];
    if (p0 == p1) return;
    const float* wp = g_Wh + (size_t)c*NH;
    float whv[16];
#pragma unroll
    for (int h = 0; h < 8; h++){
        whv[h]     = wp[h*64 + lane];
        whv[8 + h] = wp[h*64 + 32 + lane];
    }
    int p = p0;
    for (; p + 2 <= p1; p += 2){
        float wv = 0.f;
        if (lane < 16) wv = sc[lane & 7] * g_w[(size_t)(p + (lane >> 3))*8 + (lane & 7)];
        float a00 = 0.f, a01 = 0.f, a10 = 0.f, a11 = 0.f;
#pragma unroll
        for (int h = 0; h < 8; h++){
            float w0 = __shfl_sync(0xffffffffu, wv, h);
            float w1 = __shfl_sync(0xffffffffu, wv, 8 + h);
            a00 += w0 * whv[h];
            a01 += w0 * whv[8 + h];
            a10 += w1 * whv[h];
            a11 += w1 * whv[8 + h];
        }
        int r0 = g_srow[p], r1 = g_srow[p+1];
        atomicAdd(out + (size_t)r0*64 + lane,      a00);
        atomicAdd(out + (size_t)r0*64 + 32 + lane, a01);
        atomicAdd(out + (size_t)r1*64 + lane,      a10);
        atomicAdd(out + (size_t)r1*64 + 32 + lane, a11);
    }
    if (p < p1){
        float wv = 0.f;
        if (lane < 8) wv = sc[lane] * g_w[(size_t)p*8 + lane];
        float a0 = 0.f, a1 = 0.f;
#pragma unroll
        for (int h = 0; h < 8; h++){
            float w = __shfl_sync(0xffffffffu, wv, h);
            a0 += w * whv[h];
            a1 += w * whv[8 + h];
        }
        int r0 = g_srow[p];
        atomicAdd(out + (size_t)r0*64 + lane,      a0);
        atomicAdd(out + (size_t)r0*64 + 32 + lane, a1);
    }
}

// ---------------- launch ----------------
extern "C" void kernel_launch(void* const* d_in, const int* in_sizes, int n_in,
                              void* d_out, int out_size){
    const float* x    = (const float*)d_in[0];
    const int*   ei   = (const int*)  d_in[1];
    const float* W    = (const float*)d_in[2];
    const float* b    = (const float*)d_in[3];
    const float* a    = (const float*)d_in[4];
    const float* gate = (const float*)d_in[5];
    float* out = (float*)d_out;

    cudaFuncSetAttribute(k_big, cudaFuncAttributeMaxDynamicSharedMemorySize, SMEM_BIG);

    k_setup<<<(NPAD*IN_DIM/4 + 255)/256, 256>>>(x, ei, W, gate, out);
    k_scan1<<<(NNODES + 255)/256, 256>>>();
    k_scan2<<<1, 256>>>();
    k_scan3<<<(NNODES + 255)/256, 256>>>();
    dim3 gg(NPAD/128, 4);
    k_big<<<gg, 256, SMEM_BIG>>>(b, a, ei);
    k_e<<<NEDGES/256, 256>>>();
    k_scatter<<<(NNODES + 7)/8, 256>>>(out);
}